// round 1
// baseline (speedup 1.0000x reference)
#include <cuda_runtime.h>
#include <math.h>

#define C_IN 256
#define NPOS 4096
#define NB   8
#define DQK  32
#define DV   256
#define BQ   64
#define BK   64

// Scratch (allocation-free rule: __device__ globals)
__device__ float g_f[NB * NPOS * DQK];   // K (keys)   [b][n][32]
__device__ float g_g[NB * NPOS * DQK];   // Q (queries)[b][m][32]
__device__ float g_h[NB * NPOS * DV];    // V (values) [b][n][256]

// ---- packed f32x2 helpers (FFMA2: 2x fp32 throughput, PTX-only) ----
__device__ __forceinline__ unsigned long long pk2(float a, float b) {
    unsigned long long r;
    asm("mov.b64 %0, {%1,%2};" : "=l"(r) : "f"(a), "f"(b));
    return r;
}
__device__ __forceinline__ float2 up2(unsigned long long v) {
    float2 r;
    asm("mov.b64 {%0,%1}, %2;" : "=f"(r.x), "=f"(r.y) : "l"(v));
    return r;
}
__device__ __forceinline__ void fma2(unsigned long long &d, unsigned long long a, unsigned long long b) {
    asm("fma.rn.f32x2 %0, %1, %2, %0;" : "+l"(d) : "l"(a), "l"(b));
}
__device__ __forceinline__ void mul2(unsigned long long &d, unsigned long long a, unsigned long long b) {
    asm("mul.rn.f32x2 %0, %1, %2;" : "=l"(d) : "l"(a), "l"(b));
}

// ============================================================================
// Projection: out[b][n][co] = sum_c w[co][c] * x[b][c][n] + bias[co]
// Block: 256 threads (16 tx = n-quads, 16 ty = co-slabs), n-tile = 64.
// ============================================================================
template <int CO>
__global__ void proj_kernel(const float* __restrict__ x,
                            const float* __restrict__ w,
                            const float* __restrict__ bias,
                            float* __restrict__ out) {
    __shared__ float xs[32 * 64];     // [cc][nn]
    __shared__ float ws[CO * 32];     // [co][cc]
    const int tid = threadIdx.x;
    const int tx = tid & 15, ty = tid >> 4;
    const int b  = blockIdx.y;
    const int n0 = blockIdx.x * 64;
    constexpr int J = CO / 16;

    unsigned long long acc[J][2];
#pragma unroll
    for (int j = 0; j < J; j++) { acc[j][0] = 0ull; acc[j][1] = 0ull; }

    for (int cb = 0; cb < C_IN; cb += 32) {
        __syncthreads();
        for (int i = tid; i < 512; i += 256) {
            int cc = i >> 4, nq = i & 15;
            ((float4*)xs)[cc * 16 + nq] =
                *(const float4*)&x[((size_t)b * C_IN + cb + cc) * NPOS + n0 + nq * 4];
        }
        for (int i = tid; i < CO * 8; i += 256) {
            int co = i >> 3, c4 = i & 7;
            ((float4*)ws)[i] = *(const float4*)&w[co * C_IN + cb + c4 * 4];
        }
        __syncthreads();
#pragma unroll 4
        for (int cc = 0; cc < 32; cc++) {
            ulonglong2 xv = *(ulonglong2*)&xs[cc * 64 + tx * 4];
#pragma unroll
            for (int j = 0; j < J; j++) {
                float wv_ = ws[(ty * J + j) * 32 + cc];
                unsigned long long wp = pk2(wv_, wv_);
                fma2(acc[j][0], xv.x, wp);
                fma2(acc[j][1], xv.y, wp);
            }
        }
    }
#pragma unroll
    for (int j = 0; j < J; j++) {
        int co = ty * J + j;
        float bv_ = bias[co];
        float2 a0 = up2(acc[j][0]), a1 = up2(acc[j][1]);
        size_t base = (size_t)b * NPOS + n0 + tx * 4;
        out[(base + 0) * CO + co] = a0.x + bv_;
        out[(base + 1) * CO + co] = a0.y + bv_;
        out[(base + 2) * CO + co] = a1.x + bv_;
        out[(base + 3) * CO + co] = a1.y + bv_;
    }
}

// ============================================================================
// Flash attention: Q=g, K=f, V=h, no scale. Online softmax over keys (axis n).
// Block: 256 threads = 8 warps. Each warp owns 8 queries; each lane owns
// value channels {4l..4l+3} and {128+4l..128+4l+3}. Accumulators packed f32x2.
// Grid: (N/BQ, B).
// ============================================================================
__global__ void attn_kernel(const float* __restrict__ Kg,
                            const float* __restrict__ Qg,
                            const float* __restrict__ Vg,
                            float* __restrict__ out) {
    extern __shared__ float sm[];
    float* Qs = sm;                       // 64*32
    float* Ks = sm + 2048;                // 64*32
    float* Ss = sm + 4096;                // 64*68 (padded rows)
    float* Vs = sm + 4096 + 64 * 68;      // 64*256

    const int tid = threadIdx.x;
    const int warp = tid >> 5, lane = tid & 31;
    const int b = blockIdx.y;
    const int m0 = blockIdx.x * BQ;

    // Load Q tile (rows contiguous in g_g)
    for (int i = tid; i < 512; i += 256)
        ((float4*)Qs)[i] = *(const float4*)&Qg[((size_t)b * NPOS + m0) * DQK + i * 4];

    float mrow[8], lrow[8];
    unsigned long long Oacc[8][4];
#pragma unroll
    for (int i = 0; i < 8; i++) {
        mrow[i] = -INFINITY; lrow[i] = 0.f;
#pragma unroll
        for (int k = 0; k < 4; k++) Oacc[i][k] = 0ull;
    }

    const int tq = (tid >> 4) * 4, tn = (tid & 15) * 4;

    for (int kb = 0; kb < NPOS; kb += BK) {
        __syncthreads();   // prior chunk's P/V reads complete before overwrite
        for (int i = tid; i < 512; i += 256)
            ((float4*)Ks)[i] = *(const float4*)&Kg[((size_t)b * NPOS + kb) * DQK + i * 4];
        for (int i = tid; i < 4096; i += 256)
            ((float4*)Vs)[i] = *(const float4*)&Vg[((size_t)b * NPOS + kb) * DV + i * 4];
        __syncthreads();

        // ---- S = Q K^T  (thread computes 4q x 4n) ----
        float sacc[4][4];
#pragma unroll
        for (int i2 = 0; i2 < 4; i2++)
#pragma unroll
            for (int j2 = 0; j2 < 4; j2++) sacc[i2][j2] = 0.f;

#pragma unroll
        for (int c = 0; c < 32; c += 4) {
            float4 qv[4], kv[4];
#pragma unroll
            for (int i2 = 0; i2 < 4; i2++) qv[i2] = *(float4*)&Qs[(tq + i2) * DQK + c];
#pragma unroll
            for (int j2 = 0; j2 < 4; j2++) kv[j2] = *(float4*)&Ks[(tn + j2) * DQK + c];
#pragma unroll
            for (int i2 = 0; i2 < 4; i2++)
#pragma unroll
                for (int j2 = 0; j2 < 4; j2++)
                    sacc[i2][j2] += qv[i2].x * kv[j2].x + qv[i2].y * kv[j2].y +
                                    qv[i2].z * kv[j2].z + qv[i2].w * kv[j2].w;
        }
#pragma unroll
        for (int i2 = 0; i2 < 4; i2++)
            *(float4*)&Ss[(tq + i2) * 68 + tn] =
                make_float4(sacc[i2][0], sacc[i2][1], sacc[i2][2], sacc[i2][3]);
        __syncthreads();

        // ---- online softmax (warp-local: warp owns rows warp*8..warp*8+7) ----
#pragma unroll
        for (int i = 0; i < 8; i++) {
            int q = warp * 8 + i;
            float2 sv = *(float2*)&Ss[q * 68 + lane * 2];
            float cm = fmaxf(sv.x, sv.y);
#pragma unroll
            for (int off = 16; off > 0; off >>= 1)
                cm = fmaxf(cm, __shfl_xor_sync(0xffffffffu, cm, off));
            float nm = fmaxf(mrow[i], cm);
            float e0 = __expf(sv.x - nm), e1 = __expf(sv.y - nm);
            *(float2*)&Ss[q * 68 + lane * 2] = make_float2(e0, e1);
            float rs = e0 + e1;
#pragma unroll
            for (int off = 16; off > 0; off >>= 1)
                rs += __shfl_xor_sync(0xffffffffu, rs, off);
            float sc = __expf(mrow[i] - nm);
            lrow[i] = lrow[i] * sc + rs;
            mrow[i] = nm;
            unsigned long long sp = pk2(sc, sc);
#pragma unroll
            for (int k = 0; k < 4; k++) mul2(Oacc[i][k], Oacc[i][k], sp);
        }
        __syncwarp();

        // ---- O += P V  (FFMA2 mainloop) ----
#pragma unroll 2
        for (int n4 = 0; n4 < 16; n4++) {
            float pr[8][4];
#pragma unroll
            for (int i = 0; i < 8; i++) {
                float4 p4 = *(float4*)&Ss[(warp * 8 + i) * 68 + n4 * 4];
                pr[i][0] = p4.x; pr[i][1] = p4.y; pr[i][2] = p4.z; pr[i][3] = p4.w;
            }
#pragma unroll
            for (int t = 0; t < 4; t++) {
                int n = n4 * 4 + t;
                ulonglong2 va = *(ulonglong2*)&Vs[n * DV + lane * 4];
                ulonglong2 vb = *(ulonglong2*)&Vs[n * DV + 128 + lane * 4];
#pragma unroll
                for (int i = 0; i < 8; i++) {
                    unsigned long long pp = pk2(pr[i][t], pr[i][t]);
                    fma2(Oacc[i][0], va.x, pp);
                    fma2(Oacc[i][1], va.y, pp);
                    fma2(Oacc[i][2], vb.x, pp);
                    fma2(Oacc[i][3], vb.y, pp);
                }
            }
        }
    }

    // ---- epilogue: normalize, transpose via smem, coalesced store ----
    __syncthreads();                 // all PV reads of Vs/Ss complete
    float* Os = sm + 2048;           // overlay (needs 256*68=17408 <= 22784)
#pragma unroll
    for (int i = 0; i < 8; i++) {
        int q = warp * 8 + i;
        float inv = 1.0f / lrow[i];
#pragma unroll
        for (int k = 0; k < 4; k++) {
            float2 vv = up2(Oacc[i][k]);
            int c = (k & 1) * 2 + (k >> 1) * 128 + lane * 4;
            Os[c * 68 + q]       = vv.x * inv;
            Os[(c + 1) * 68 + q] = vv.y * inv;
        }
    }
    __syncthreads();
    for (int i = tid; i < 4096; i += 256) {   // 256 c x 16 q-quads
        int c = i >> 4, q4 = i & 15;
        float4 v = *(float4*)&Os[c * 68 + q4 * 4];
        *(float4*)&out[((size_t)b * C_IN + c) * NPOS + m0 + q4 * 4] = v;
    }
}

// ============================================================================
extern "C" void kernel_launch(void* const* d_in, const int* in_sizes, int n_in,
                              void* d_out, int out_size) {
    const float* x  = (const float*)d_in[0];
    const float* wq = (const float*)d_in[1];
    const float* bq = (const float*)d_in[2];
    const float* wk = (const float*)d_in[3];
    const float* bk = (const float*)d_in[4];
    const float* wv = (const float*)d_in[5];
    const float* bv = (const float*)d_in[6];
    float* out = (float*)d_out;

    float *fP, *gP, *hP;
    cudaGetSymbolAddress((void**)&fP, g_f);
    cudaGetSymbolAddress((void**)&gP, g_g);
    cudaGetSymbolAddress((void**)&hP, g_h);

    dim3 grid(NPOS / 64, NB);
    proj_kernel<32><<<grid, 256>>>(x, wq, bq, fP);    // f (keys)
    proj_kernel<32><<<grid, 256>>>(x, wk, bk, gP);    // g (queries)
    proj_kernel<256><<<grid, 256>>>(x, wv, bv, hP);   // h (values)

    int smem = (2048 + 2048 + 64 * 68 + 64 * 256) * 4;   // 99328 B
    cudaFuncSetAttribute(attn_kernel, cudaFuncAttributeMaxDynamicSharedMemorySize, smem);
    attn_kernel<<<grid, 256, smem>>>(fP, gP, hP, out);
}

// round 5
// speedup vs baseline: 4.2730x; 4.2730x over previous
#include <cuda_runtime.h>
#include <cuda_bf16.h>
#include <math.h>
#include <stdint.h>

#define C_IN 256
#define NPOS 4096
#define NB   8
#define DQK  32
#define DV   256
#define BQ   128
#define BK   64
#define NCHUNK (NPOS / BK)       // 64
#define MBLKS  (NPOS / BQ)       // 32

#define QT_BYTES 16384           // 128 rows x 128B (32c hi | 32c lo per row)
#define KT_BYTES 8192            // 64 key-rows x 128B (hi | lo)
#define VT_BYTES 65536           // hi plane: 256 c-rows x 128B (64 keys), lo at +32768

__device__ unsigned char g_qt[NB * MBLKS * QT_BYTES];    // Q = g (wk proj)
__device__ unsigned char g_kt[NB * NCHUNK * KT_BYTES];   // K = f (wq proj)
__device__ unsigned char g_vt[NB * NCHUNK * VT_BYTES];   // V = h (wv proj), [c][key]

// ---------------- helpers ----------------
__device__ __forceinline__ uint32_t SW(uint32_t off) {   // SW128: col16 ^= row&7
    return off ^ ((off >> 3) & 0x70);
}
__device__ __forceinline__ uint32_t smem_u32(const void* p) {
    uint32_t a;
    asm("{ .reg .u64 t; cvta.to.shared.u64 t, %1; cvt.u32.u64 %0, t; }" : "=r"(a) : "l"(p));
    return a;
}
__device__ __forceinline__ void split2(float a, float b, uint32_t& hi, uint32_t& lo) {
    __nv_bfloat16 ha = __float2bfloat16(a), hb = __float2bfloat16(b);
    __nv_bfloat162 hh; hh.x = ha; hh.y = hb;
    hi = *reinterpret_cast<uint32_t*>(&hh);
    __nv_bfloat162 ll;
    ll.x = __float2bfloat16(a - __bfloat162float(ha));
    ll.y = __float2bfloat16(b - __bfloat162float(hb));
    lo = *reinterpret_cast<uint32_t*>(&ll);
}
__device__ __forceinline__ unsigned long long pk2(float a, float b) {
    unsigned long long r;
    asm("mov.b64 %0, {%1,%2};" : "=l"(r) : "f"(a), "f"(b));
    return r;
}
__device__ __forceinline__ float2 up2(unsigned long long v) {
    float2 r;
    asm("mov.b64 {%0,%1}, %2;" : "=f"(r.x), "=f"(r.y) : "l"(v));
    return r;
}
__device__ __forceinline__ void fma2(unsigned long long &d, unsigned long long a, unsigned long long b) {
    asm("fma.rn.f32x2 %0, %1, %2, %0;" : "+l"(d) : "l"(a), "l"(b));
}
__device__ __forceinline__ void mbar_init(uint32_t mbar, uint32_t cnt) {
    asm volatile("mbarrier.init.shared.b64 [%0], %1;" :: "r"(mbar), "r"(cnt) : "memory");
}
__device__ __forceinline__ void mbar_expect(uint32_t mbar, uint32_t bytes) {
    asm volatile("mbarrier.arrive.expect_tx.shared.b64 _, [%0], %1;" :: "r"(mbar), "r"(bytes) : "memory");
}
__device__ __forceinline__ void mbar_wait(uint32_t mbar, int phase) {
    asm volatile(
        "{\n\t.reg .pred P1;\n\t"
        "LAB_WAIT_%=:\n\t"
        "mbarrier.try_wait.parity.acquire.cta.shared::cta.b64 P1, [%0], %1, 0x989680;\n\t"
        "@P1 bra LAB_DONE_%=;\n\t"
        "bra LAB_WAIT_%=;\n\t"
        "LAB_DONE_%=:\n\t}"
        :: "r"(mbar), "r"((uint32_t)phase) : "memory");
}
__device__ __forceinline__ void bulk_g2s(uint32_t dst, const void* src, uint32_t bytes, uint32_t mbar) {
    asm volatile(
        "cp.async.bulk.shared::cluster.global.mbarrier::complete_tx::bytes [%0], [%1], %2, [%3];"
        :: "r"(dst), "l"(src), "r"(bytes), "r"(mbar) : "memory");
}
__device__ __forceinline__ void sts32(uint32_t a, uint32_t v) {
    asm volatile("st.shared.b32 [%0], %1;" :: "r"(a), "r"(v));
}
__device__ __forceinline__ void ldsm4(uint32_t& r0, uint32_t& r1, uint32_t& r2, uint32_t& r3,
                                      uint32_t addr) {
    asm volatile("ldmatrix.sync.aligned.m8n8.x4.shared.b16 {%0,%1,%2,%3}, [%4];"
                 : "=r"(r0), "=r"(r1), "=r"(r2), "=r"(r3) : "r"(addr));
}
__device__ __forceinline__ void mma16816(float* c, uint32_t a0, uint32_t a1, uint32_t a2, uint32_t a3,
                                         uint32_t b0, uint32_t b1) {
    asm volatile(
        "mma.sync.aligned.m16n8k16.row.col.f32.bf16.bf16.f32 "
        "{%0,%1,%2,%3}, {%4,%5,%6,%7}, {%8,%9}, {%0,%1,%2,%3};"
        : "+f"(c[0]), "+f"(c[1]), "+f"(c[2]), "+f"(c[3])
        : "r"(a0), "r"(a1), "r"(a2), "r"(a3), "r"(b0), "r"(b1));
}

// ============================================================================
// Projections: out[b][n][co] = sum_c w[co][c]*x[b][c][n] + bias[co]
// Emit pre-swizzled split-bf16 tiles.
// ============================================================================
template <bool ISQ>
__global__ void proj_qk_kernel(const float* __restrict__ x, const float* __restrict__ w,
                               const float* __restrict__ bias, unsigned char* __restrict__ dst) {
    __shared__ float xs[32 * 64];
    __shared__ float ws[32 * 32];
    const int tid = threadIdx.x;
    const int tx = tid & 15, ty = tid >> 4;
    const int b  = blockIdx.y;
    const int n0 = blockIdx.x * 64;

    unsigned long long acc[2][2];
#pragma unroll
    for (int j = 0; j < 2; j++) { acc[j][0] = 0ull; acc[j][1] = 0ull; }

    for (int cb = 0; cb < C_IN; cb += 32) {
        __syncthreads();
        for (int i = tid; i < 512; i += 256) {
            int cc = i >> 4, nq = i & 15;
            ((float4*)xs)[cc * 16 + nq] =
                *(const float4*)&x[((size_t)b * C_IN + cb + cc) * NPOS + n0 + nq * 4];
        }
        {
            int co = tid >> 3, c4 = tid & 7;
            ((float4*)ws)[tid] = *(const float4*)&w[co * C_IN + cb + c4 * 4];
        }
        __syncthreads();
#pragma unroll 4
        for (int cc = 0; cc < 32; cc++) {
            ulonglong2 xv = *(ulonglong2*)&xs[cc * 64 + tx * 4];
#pragma unroll
            for (int j = 0; j < 2; j++) {
                float wv_ = ws[(ty * 2 + j) * 32 + cc];
                unsigned long long wp = pk2(wv_, wv_);
                fma2(acc[j][0], xv.x, wp);
                fma2(acc[j][1], xv.y, wp);
            }
        }
    }
    const int co0 = ty * 2;
    const float bv0 = bias[co0], bv1 = bias[co0 + 1];
    float a0[4], a1[4];
    { float2 t = up2(acc[0][0]); a0[0] = t.x + bv0; a0[1] = t.y + bv0;
      t = up2(acc[0][1]); a0[2] = t.x + bv0; a0[3] = t.y + bv0; }
    { float2 t = up2(acc[1][0]); a1[0] = t.x + bv1; a1[1] = t.y + bv1;
      t = up2(acc[1][1]); a1[2] = t.x + bv1; a1[3] = t.y + bv1; }
#pragma unroll
    for (int r = 0; r < 4; r++) {
        int n = n0 + tx * 4 + r;
        uint32_t hi, lo;
        split2(a0[r], a1[r], hi, lo);
        size_t tb; uint32_t row;
        if (ISQ) { tb = ((size_t)b * MBLKS  + (n >> 7)) * QT_BYTES; row = n & 127; }
        else     { tb = ((size_t)b * NCHUNK + (n >> 6)) * KT_BYTES; row = n & 63;  }
        *(uint32_t*)(dst + tb + SW(row * 128 + co0 * 2))       = hi;
        *(uint32_t*)(dst + tb + SW(row * 128 + 64 + co0 * 2))  = lo;
    }
}

__global__ void proj_v_kernel(const float* __restrict__ x, const float* __restrict__ w,
                              const float* __restrict__ bias, unsigned char* __restrict__ dst) {
    __shared__ float xs[32 * 64];
    __shared__ float ws[256 * 32];
    const int tid = threadIdx.x;
    const int tx = tid & 15, ty = tid >> 4;
    const int b  = blockIdx.y;
    const int n0 = blockIdx.x * 64;

    unsigned long long acc[16][2];
#pragma unroll
    for (int j = 0; j < 16; j++) { acc[j][0] = 0ull; acc[j][1] = 0ull; }

    for (int cb = 0; cb < C_IN; cb += 32) {
        __syncthreads();
        for (int i = tid; i < 512; i += 256) {
            int cc = i >> 4, nq = i & 15;
            ((float4*)xs)[cc * 16 + nq] =
                *(const float4*)&x[((size_t)b * C_IN + cb + cc) * NPOS + n0 + nq * 4];
        }
        for (int i = tid; i < 2048; i += 256) {
            int co = i >> 3, c4 = i & 7;
            ((float4*)ws)[i] = *(const float4*)&w[co * C_IN + cb + c4 * 4];
        }
        __syncthreads();
#pragma unroll 4
        for (int cc = 0; cc < 32; cc++) {
            ulonglong2 xv = *(ulonglong2*)&xs[cc * 64 + tx * 4];
#pragma unroll
            for (int j = 0; j < 16; j++) {
                float wv_ = ws[(ty * 16 + j) * 32 + cc];
                unsigned long long wp = pk2(wv_, wv_);
                fma2(acc[j][0], xv.x, wp);
                fma2(acc[j][1], xv.y, wp);
            }
        }
    }
    const size_t tb = ((size_t)b * NCHUNK + (n0 >> 6)) * VT_BYTES;
#pragma unroll
    for (int j = 0; j < 16; j++) {
        int co = ty * 16 + j;
        float bv = bias[co];
        float v[4];
        { float2 t = up2(acc[j][0]); v[0] = t.x + bv; v[1] = t.y + bv;
          t = up2(acc[j][1]); v[2] = t.x + bv; v[3] = t.y + bv; }
        uint32_t h0, l0, h1, l1;
        split2(v[0], v[1], h0, l0);
        split2(v[2], v[3], h1, l1);
        uint32_t off = SW((uint32_t)co * 128 + tx * 8);
        *(uint2*)(dst + tb + off)          = make_uint2(h0, h1);
        *(uint2*)(dst + tb + 32768 + off)  = make_uint2(l0, l1);
    }
}

// ============================================================================
// mma.sync attention. 256 thr / 8 warps: warp w -> qg=w&3 (32 q rows),
// nh=w>>2 (32-key S slice, 128-channel V slice). Unnormalized exp; O in regs.
// ============================================================================
__global__ void __launch_bounds__(256, 1)
attn_kernel(const unsigned char* __restrict__ qt, const unsigned char* __restrict__ kt,
            const unsigned char* __restrict__ vt, float* __restrict__ out) {
    extern __shared__ __align__(1024) unsigned char sm[];
    const uint32_t sb = smem_u32(sm);
    const int tid  = threadIdx.x;
    const int lane = tid & 31;
    const int warp = tid >> 5;
    const int qg = warp & 3, nh = warp >> 2;
    const int b = blockIdx.y, mblk = blockIdx.x;
    const int m0 = mblk * BQ;

    const uint32_t OFF_LD0 = 0, OFF_LD1 = 8;
    const uint32_t OFF_Q = 1024;                  // 16KB
    const uint32_t OFF_K0 = 17408, OFF_K1 = 25600;
    const uint32_t OFF_PH = 33792, OFF_PL = 50176;  // 16KB each
    const uint32_t OFF_V0 = 66560, OFF_V1 = 132096; // 64KB each

    if (tid == 0) { mbar_init(sb + OFF_LD0, 1); mbar_init(sb + OFF_LD1, 1); }
    // copy pre-swizzled Q tile
    {
        const uint4* s = (const uint4*)(qt + (size_t)(b * MBLKS + mblk) * QT_BYTES);
        uint4* d = (uint4*)(sm + OFF_Q);
        for (int i = tid; i < 1024; i += 256) d[i] = s[i];
    }
    __syncthreads();

    // kick off chunk 0
    if (tid == 0) {
        mbar_expect(sb + OFF_LD0, KT_BYTES + VT_BYTES);
        bulk_g2s(sb + OFF_K0, kt + (size_t)b * NCHUNK * KT_BYTES, KT_BYTES, sb + OFF_LD0);
        bulk_g2s(sb + OFF_V0, vt + (size_t)b * NCHUNK * VT_BYTES, VT_BYTES, sb + OFF_LD0);
    }

    // persistent Q fragments: [mi][ks][hb][4]
    uint32_t Qf[2][2][2][4];
    {
        const int q0b = qg * 32;
#pragma unroll
        for (int mi = 0; mi < 2; mi++)
#pragma unroll
            for (int ks = 0; ks < 2; ks++)
#pragma unroll
                for (int hb = 0; hb < 2; hb++) {
                    uint32_t row = q0b + mi * 16 + (lane & 7) + ((lane >> 3) & 1) * 8;
                    uint32_t off = hb * 64 + ks * 32 + (lane >> 4) * 16;
                    ldsm4(Qf[mi][ks][hb][0], Qf[mi][ks][hb][1], Qf[mi][ks][hb][2], Qf[mi][ks][hb][3],
                          sb + OFF_Q + SW(row * 128 + off));
                }
    }

    float o[2][16][4];
#pragma unroll
    for (int mi = 0; mi < 2; mi++)
#pragma unroll
        for (int n = 0; n < 16; n++)
#pragma unroll
            for (int e = 0; e < 4; e++) o[mi][n][e] = 0.f;
    float lsum[2][2] = {{0.f, 0.f}, {0.f, 0.f}};

    int ph_ld[2] = {0, 0};
    const int g = lane >> 2, t = lane & 3;

    for (int ich = 0; ich < NCHUNK; ich++) {
        const int buf = ich & 1;
        const uint32_t kOff = buf ? OFF_K1 : OFF_K0;
        const uint32_t vOff = buf ? OFF_V1 : OFF_V0;

        // prefetch next chunk into other buffer (safe: freed at end of prev iter)
        if (tid == 0 && ich + 1 < NCHUNK) {
            const uint32_t ldn = sb + (buf ? OFF_LD0 : OFF_LD1);
            mbar_expect(ldn, KT_BYTES + VT_BYTES);
            bulk_g2s(sb + (buf ? OFF_K0 : OFF_K1),
                     kt + (size_t)(b * NCHUNK + ich + 1) * KT_BYTES, KT_BYTES, ldn);
            bulk_g2s(sb + (buf ? OFF_V0 : OFF_V1),
                     vt + (size_t)(b * NCHUNK + ich + 1) * VT_BYTES, VT_BYTES, ldn);
        }
        mbar_wait(sb + (buf ? OFF_LD1 : OFF_LD0), ph_ld[buf]);
        ph_ld[buf] ^= 1;

        // ---- S = Q K^T on 32q x 32k slice; exp; write split-bf16 P ----
#pragma unroll
        for (int j = 0; j < 4; j++) {
            const uint32_t krow = nh * 32 + j * 8 + (lane & 7);
            const uint32_t koff = (lane >> 3) * 16;
            uint32_t kh[4], kl[4];
            ldsm4(kh[0], kh[1], kh[2], kh[3], sb + kOff + SW(krow * 128 + koff));
            ldsm4(kl[0], kl[1], kl[2], kl[3], sb + kOff + SW(krow * 128 + 64 + koff));

            float cs[2][4];
#pragma unroll
            for (int mi = 0; mi < 2; mi++) {
#pragma unroll
                for (int e = 0; e < 4; e++) cs[mi][e] = 0.f;
#pragma unroll
                for (int ks = 0; ks < 2; ks++) {
                    mma16816(cs[mi], Qf[mi][ks][0][0], Qf[mi][ks][0][1], Qf[mi][ks][0][2], Qf[mi][ks][0][3],
                             kh[2 * ks], kh[2 * ks + 1]);
                    mma16816(cs[mi], Qf[mi][ks][0][0], Qf[mi][ks][0][1], Qf[mi][ks][0][2], Qf[mi][ks][0][3],
                             kl[2 * ks], kl[2 * ks + 1]);
                    mma16816(cs[mi], Qf[mi][ks][1][0], Qf[mi][ks][1][1], Qf[mi][ks][1][2], Qf[mi][ks][1][3],
                             kh[2 * ks], kh[2 * ks + 1]);
                }
            }
            // exp + split + store to P
            const uint32_t keyb = (uint32_t)(nh * 64 + j * 16 + 4 * t);   // key0*2 bytes
#pragma unroll
            for (int mi = 0; mi < 2; mi++) {
                const uint32_t row0 = qg * 32 + mi * 16 + g;
                float e0 = __expf(cs[mi][0]), e1 = __expf(cs[mi][1]);
                float e2 = __expf(cs[mi][2]), e3 = __expf(cs[mi][3]);
                lsum[mi][0] += e0 + e1;
                lsum[mi][1] += e2 + e3;
                uint32_t hi, lo;
                split2(e0, e1, hi, lo);
                uint32_t sw0 = SW(row0 * 128 + keyb);
                sts32(sb + OFF_PH + sw0, hi);
                sts32(sb + OFF_PL + sw0, lo);
                split2(e2, e3, hi, lo);
                uint32_t sw1 = SW((row0 + 8) * 128 + keyb);
                sts32(sb + OFF_PH + sw1, hi);
                sts32(sb + OFF_PL + sw1, lo);
            }
        }
        __syncthreads();

        // ---- O += P V  (3-term split) ----
#pragma unroll
        for (int ks = 0; ks < 4; ks++) {
            uint32_t Ph[2][4], Pl[2][4];
            const uint32_t prow = qg * 32 + (lane & 7) + ((lane >> 3) & 1) * 8;
            const uint32_t poff = ks * 32 + (lane >> 4) * 16;
#pragma unroll
            for (int mi = 0; mi < 2; mi++) {
                uint32_t sw = SW((prow + mi * 16) * 128 + poff);
                ldsm4(Ph[mi][0], Ph[mi][1], Ph[mi][2], Ph[mi][3], sb + OFF_PH + sw);
                ldsm4(Pl[mi][0], Pl[mi][1], Pl[mi][2], Pl[mi][3], sb + OFF_PL + sw);
            }
            const uint32_t vrow0 = nh * 128 + (lane & 7) + (lane >> 4) * 8;
            const uint32_t voff  = ks * 32 + ((lane >> 3) & 1) * 16;
#pragma unroll
            for (int jn = 0; jn < 8; jn++) {
                uint32_t vh[4], vl[4];
                uint32_t sw = SW((vrow0 + jn * 16) * 128 + voff);
                ldsm4(vh[0], vh[1], vh[2], vh[3], sb + vOff + sw);
                ldsm4(vl[0], vl[1], vl[2], vl[3], sb + vOff + 32768 + sw);
#pragma unroll
                for (int mi = 0; mi < 2; mi++) {
#pragma unroll
                    for (int nt = 0; nt < 2; nt++) {
                        float* oo = o[mi][jn * 2 + nt];
                        mma16816(oo, Ph[mi][0], Ph[mi][1], Ph[mi][2], Ph[mi][3], vh[nt * 2], vh[nt * 2 + 1]);
                        mma16816(oo, Ph[mi][0], Ph[mi][1], Ph[mi][2], Ph[mi][3], vl[nt * 2], vl[nt * 2 + 1]);
                        mma16816(oo, Pl[mi][0], Pl[mi][1], Pl[mi][2], Pl[mi][3], vh[nt * 2], vh[nt * 2 + 1]);
                    }
                }
            }
        }
        __syncthreads();
    }

    // ---- epilogue: reduce row sums, normalize, transpose, store ----
    float* Ls = (float*)(sm + OFF_PH);     // [2][128]
#pragma unroll
    for (int mi = 0; mi < 2; mi++)
#pragma unroll
        for (int r = 0; r < 2; r++) {
            float v = lsum[mi][r];
            v += __shfl_xor_sync(0xffffffffu, v, 1);
            v += __shfl_xor_sync(0xffffffffu, v, 2);
            if (t == 0) Ls[nh * 128 + qg * 32 + mi * 16 + r * 8 + g] = v;
        }
    __syncthreads();
    float inv[2][2];
#pragma unroll
    for (int mi = 0; mi < 2; mi++)
#pragma unroll
        for (int r = 0; r < 2; r++) {
            int row = qg * 32 + mi * 16 + r * 8 + g;
            inv[mi][r] = 1.0f / (Ls[row] + Ls[128 + row]);
        }

    float* St = (float*)(sm + OFF_V0);     // [256][68]
#pragma unroll
    for (int mi = 0; mi < 2; mi++) {
        __syncthreads();
#pragma unroll
        for (int n = 0; n < 16; n++) {
            int cb = nh * 128 + n * 8 + 2 * t;
            int s0 = qg * 16 + g;
            St[cb * 68 + s0]           = o[mi][n][0] * inv[mi][0];
            St[(cb + 1) * 68 + s0]     = o[mi][n][1] * inv[mi][0];
            St[cb * 68 + s0 + 8]       = o[mi][n][2] * inv[mi][1];
            St[(cb + 1) * 68 + s0 + 8] = o[mi][n][3] * inv[mi][1];
        }
        __syncthreads();
        for (int i = tid; i < 4096; i += 256) {
            int c = i >> 4, s4 = i & 15;
            float4 v = *(float4*)&St[c * 68 + s4 * 4];
            int q = (s4 >> 2) * 32 + mi * 16 + (s4 & 3) * 4;
            *(float4*)&out[((size_t)b * C_IN + c) * NPOS + m0 + q] = v;
        }
    }
}

// ============================================================================
extern "C" void kernel_launch(void* const* d_in, const int* in_sizes, int n_in,
                              void* d_out, int out_size) {
    (void)in_sizes; (void)n_in; (void)out_size;
    const float* x  = (const float*)d_in[0];
    const float* wq = (const float*)d_in[1];
    const float* bq = (const float*)d_in[2];
    const float* wk = (const float*)d_in[3];
    const float* bk = (const float*)d_in[4];
    const float* wv = (const float*)d_in[5];
    const float* bv = (const float*)d_in[6];
    float* out = (float*)d_out;

    unsigned char *qtP, *ktP, *vtP;
    cudaGetSymbolAddress((void**)&qtP, g_qt);
    cudaGetSymbolAddress((void**)&ktP, g_kt);
    cudaGetSymbolAddress((void**)&vtP, g_vt);

    dim3 pgrid(NPOS / 64, NB);
    proj_qk_kernel<false><<<pgrid, 256>>>(x, wq, bq, ktP);   // f = keys
    proj_qk_kernel<true ><<<pgrid, 256>>>(x, wk, bk, qtP);   // g = queries
    proj_v_kernel<<<pgrid, 256>>>(x, wv, bv, vtP);           // h = values

    const int smem = 197632;
    cudaFuncSetAttribute(attn_kernel, cudaFuncAttributeMaxDynamicSharedMemorySize, smem);
    attn_kernel<<<dim3(MBLKS, NB), 256, smem>>>(qtP, ktP, vtP, out);
}